// round 2
// baseline (speedup 1.0000x reference)
#include <cuda_runtime.h>

// SpikingLayer: input [2048, 16384] fp32 viewed as [T=64, B=32, F=16384].
// Per (b,f), replicating the reference bit-for-bit in fp32:
//   s = (x + s) - a
//   s = max(s + 1, 0) - 1            // relu(s - thr_low) + thr_low, thr_low = -1
//   a = (s > 0) ? floor(s) : 0
// Pure streaming recurrence: 1 load + 1 store per element, serial only in T.

#define BF4 (32 * 16384 / 4)   // B*F float4 lanes = 131072
#define TSTEPS 64

__global__ __launch_bounds__(256)
void spiking_layer_kernel(const float4* __restrict__ in,
                          float4* __restrict__ out) {
    const int i = blockIdx.x * blockDim.x + threadIdx.x;   // 0 .. BF4-1

    float4 s = make_float4(0.f, 0.f, 0.f, 0.f);
    float4 a = make_float4(0.f, 0.f, 0.f, 0.f);

    int idx = i;
    float4 x = in[idx];                    // t = 0 load

    #pragma unroll
    for (int t = 0; t < TSTEPS; ++t) {
        float4 xn;
        if (t < TSTEPS - 1) {
            xn = in[idx + BF4];            // prefetch t+1 (independent of state chain)
        }

        // membrane update: (x + s) - a, exact reference order
        s.x = (x.x + s.x) - a.x;
        s.y = (x.y + s.y) - a.y;
        s.z = (x.z + s.z) - a.z;
        s.w = (x.w + s.w) - a.w;

        // lower clamp in reference order: relu(s + 1) - 1  (NOT max(s, -1) — rounding differs)
        s.x = fmaxf(s.x + 1.0f, 0.0f) - 1.0f;
        s.y = fmaxf(s.y + 1.0f, 0.0f) - 1.0f;
        s.z = fmaxf(s.z + 1.0f, 0.0f) - 1.0f;
        s.w = fmaxf(s.w + 1.0f, 0.0f) - 1.0f;

        // threshold-subtract spike count: floor(s) when s > 0, else 0
        a.x = (s.x > 0.f) ? floorf(s.x) : 0.f;
        a.y = (s.y > 0.f) ? floorf(s.y) : 0.f;
        a.z = (s.z > 0.f) ? floorf(s.z) : 0.f;
        a.w = (s.w > 0.f) ? floorf(s.w) : 0.f;

        out[idx] = a;

        idx += BF4;
        x = xn;
    }
}

extern "C" void kernel_launch(void* const* d_in, const int* in_sizes, int n_in,
                              void* d_out, int out_size) {
    const float4* in = (const float4*)d_in[0];
    float4* out = (float4*)d_out;

    const int threads = 256;
    const int blocks = BF4 / threads;      // 512
    spiking_layer_kernel<<<blocks, threads>>>(in, out);
}

// round 3
// speedup vs baseline: 1.0391x; 1.0391x over previous
#include <cuda_runtime.h>

// SpikingLayer: input [2048, 16384] fp32 viewed as [T=64, B=32, F=16384].
// Per (b,f), replicating the reference bit-for-bit in fp32:
//   s = (x + s) - a
//   s = max(s + 1, 0) - 1            // relu(s - thr_low) + thr_low, thr_low = -1
//   a = (s > 0) ? floor(s) : 0
// DRAM-bound stream (256 MiB total, zero reuse). Depth-2 prefetch gives each
// thread 2 x 16B loads in flight -> ~4 MB chip-wide MLP (saturation needs ~3.8 MB).
// Streaming cache hints (__ldcs/__stcs): data is touched exactly once.

#define BF4 (32 * 16384 / 4)   // B*F float4 lanes = 131072
#define TSTEPS 64

__global__ __launch_bounds__(256)
void spiking_layer_kernel(const float4* __restrict__ in,
                          float4* __restrict__ out) {
    const int i = blockIdx.x * blockDim.x + threadIdx.x;   // 0 .. BF4-1

    float4 s = make_float4(0.f, 0.f, 0.f, 0.f);
    float4 a = make_float4(0.f, 0.f, 0.f, 0.f);

    int idx = i;
    float4 x0 = __ldcs(&in[idx]);              // t = 0
    float4 x1 = __ldcs(&in[idx + BF4]);        // t = 1 (in flight)

    #pragma unroll
    for (int t = 0; t < TSTEPS; ++t) {
        float4 x2;
        if (t < TSTEPS - 2) {
            x2 = __ldcs(&in[idx + 2 * BF4]);   // prefetch t+2: 2 loads always in flight
        }

        // membrane update: (x + s) - a, exact reference order
        s.x = (x0.x + s.x) - a.x;
        s.y = (x0.y + s.y) - a.y;
        s.z = (x0.z + s.z) - a.z;
        s.w = (x0.w + s.w) - a.w;

        // lower clamp in reference order: relu(s + 1) - 1 (NOT max(s,-1) — rounding differs)
        s.x = fmaxf(s.x + 1.0f, 0.0f) - 1.0f;
        s.y = fmaxf(s.y + 1.0f, 0.0f) - 1.0f;
        s.z = fmaxf(s.z + 1.0f, 0.0f) - 1.0f;
        s.w = fmaxf(s.w + 1.0f, 0.0f) - 1.0f;

        // threshold-subtract spike count: floor(s) when s > 0, else 0
        a.x = (s.x > 0.f) ? floorf(s.x) : 0.f;
        a.y = (s.y > 0.f) ? floorf(s.y) : 0.f;
        a.z = (s.z > 0.f) ? floorf(s.z) : 0.f;
        a.w = (s.w > 0.f) ? floorf(s.w) : 0.f;

        __stcs(&out[idx], a);                  // streaming store, evict-first

        idx += BF4;
        x0 = x1;
        x1 = x2;
    }
}

extern "C" void kernel_launch(void* const* d_in, const int* in_sizes, int n_in,
                              void* d_out, int out_size) {
    const float4* in = (const float4*)d_in[0];
    float4* out = (float4*)d_out;

    const int threads = 256;
    const int blocks = BF4 / threads;      // 512 blocks; all resident (885 thr/SM)
    spiking_layer_kernel<<<blocks, threads>>>(in, out);
}